// round 8
// baseline (speedup 1.0000x reference)
#include <cuda_runtime.h>
#include <cuda_bf16.h>

#define N_USERS 100000
#define N_ITEMS 50000
#define NTOT    150000
#define D       64
#define NNZ     2000000
#define BATCH   16384
#define NTILES  586            // ceil(NTOT/256)
#define CONV_BLOCKS 4688       // NTOT*D/8/256
#define HIST_BLOCKS 1954       // ceil(NNZ/4/256)

// Scratch (allocation-free: __device__ globals; zero-initialized at load)
__device__ __nv_bfloat16 d_h0[NTOT * D];   // bf16 concat(emb_user, emb_item)
__device__ __nv_bfloat16 d_h1[NTOT * D];   // layer 1 output (bf16)
__device__ __nv_bfloat16 d_h2[NTOT * D];   // layer 2 output (bf16)
__device__ float   d_b3[NTOT * D];         // layer 3 output (fp32, never gathered)
__device__ int     d_cnt [NTOT];
__device__ int     d_cur [NTOT];
__device__ int     d_rs  [NTOT + 1];
__device__ unsigned long long d_tstate[NTILES];  // lookback states: flag<<32|val
__device__ float2  d_scv [NNZ];            // packed (col_as_float_bits, val)

// ---------------------------------------------------------------------------
// k1 (fused): tobf16 | histogram | lookback-state reset
// ---------------------------------------------------------------------------
__global__ void k1_fused(const float4* __restrict__ eu,
                         const float4* __restrict__ ei,
                         const int4*   __restrict__ grow4) {
    int bid = blockIdx.x;
    if (bid < CONV_BLOCKS) {
        int i = bid * 256 + threadIdx.x;            // chunk of 8 elements
        const int total8 = NTOT * D / 8;
        if (i >= total8) return;
        const int uhalf = N_USERS * D / 8;
        float4 a, b;
        if (i < uhalf) { a = eu[i * 2]; b = eu[i * 2 + 1]; }
        else { int j = i - uhalf; a = ei[j * 2]; b = ei[j * 2 + 1]; }
        __nv_bfloat162 h[4];
        h[0] = __floats2bfloat162_rn(a.x, a.y);
        h[1] = __floats2bfloat162_rn(a.z, a.w);
        h[2] = __floats2bfloat162_rn(b.x, b.y);
        h[3] = __floats2bfloat162_rn(b.z, b.w);
        ((uint4*)d_h0)[i] = *(uint4*)h;
    } else if (bid < CONV_BLOCKS + HIST_BLOCKS) {
        int i = (bid - CONV_BLOCKS) * 256 + threadIdx.x;
        if (i >= NNZ / 4) return;
        int4 r = grow4[i];
        atomicAdd(&d_cnt[r.x], 1);
        atomicAdd(&d_cnt[r.y], 1);
        atomicAdd(&d_cnt[r.z], 1);
        atomicAdd(&d_cnt[r.w], 1);
    } else {
        int i = (bid - CONV_BLOCKS - HIST_BLOCKS) * 256 + threadIdx.x;
        if (i < NTILES) d_tstate[i] = 0ULL;
    }
}

// ---------------------------------------------------------------------------
// k2: single-pass decoupled-lookback scan of d_cnt -> d_rs (exclusive).
// Also zeroes d_cnt for the next replay and initializes d_cur = d_rs.
// ---------------------------------------------------------------------------
__global__ void k2_scan_lookback() {
    __shared__ int ws[8];
    __shared__ int s_off;
    const int tile = blockIdx.x;
    const int i = tile * 256 + threadIdx.x;
    const int lane = threadIdx.x & 31, w = threadIdx.x >> 5;

    int c = (i < NTOT) ? d_cnt[i] : 0;
    if (i < NTOT) d_cnt[i] = 0;

    int x = c;
    #pragma unroll
    for (int o = 1; o < 32; o <<= 1) {
        int y = __shfl_up_sync(0xffffffffu, x, o);
        if (lane >= o) x += y;
    }
    if (lane == 31) ws[w] = x;
    __syncthreads();
    if (w == 0) {
        int s = (lane < 8) ? ws[lane] : 0;
        #pragma unroll
        for (int o = 1; o < 8; o <<= 1) {
            int y = __shfl_up_sync(0xffffffffu, s, o);
            if (lane >= o) s += y;
        }
        if (lane < 8) ws[lane] = s;
    }
    __syncthreads();
    int woff = (w > 0) ? ws[w - 1] : 0;
    int incl = x + woff;
    int total = ws[7];

    if (threadIdx.x == 0) {
        unsigned long long st = (tile == 0)
            ? ((2ULL << 32) | (unsigned)total)
            : ((1ULL << 32) | (unsigned)total);
        *(volatile unsigned long long*)&d_tstate[tile] = st;
    }

    if (w == 0) {
        int running = 0;
        int base = tile - 1;
        while (base >= 0) {
            int idx = base - lane;
            unsigned long long st;
            int flag;
            do {
                st = (idx >= 0)
                   ? *(volatile unsigned long long*)&d_tstate[idx]
                   : (2ULL << 32);
                flag = (int)(st >> 32);
            } while (__any_sync(0xffffffffu, flag == 0));
            int val = (int)(unsigned)st;
            unsigned mask = __ballot_sync(0xffffffffu, flag == 2);
            if (mask) {
                int k = __ffs(mask) - 1;
                int contrib = (lane <= k) ? val : 0;
                #pragma unroll
                for (int o = 16; o; o >>= 1)
                    contrib += __shfl_xor_sync(0xffffffffu, contrib, o);
                running += contrib;
                break;
            } else {
                int contrib = val;
                #pragma unroll
                for (int o = 16; o; o >>= 1)
                    contrib += __shfl_xor_sync(0xffffffffu, contrib, o);
                running += contrib;
                base -= 32;
            }
        }
        if (lane == 0) {
            s_off = running;
            if (tile > 0)
                *(volatile unsigned long long*)&d_tstate[tile] =
                    (2ULL << 32) | (unsigned)(running + total);
        }
    }
    __syncthreads();

    int excl = s_off + incl - c;
    if (i <= NTOT) d_rs[i] = excl;
    if (i < NTOT)  d_cur[i] = excl;
}

// ---------------------------------------------------------------------------
// k3: permute edges into CSR order (4 edges per thread, vectorized loads)
// ---------------------------------------------------------------------------
__global__ void k3_permute(const int4*   __restrict__ grow4,
                           const int4*   __restrict__ gcol4,
                           const float4* __restrict__ gval4) {
    int i = blockIdx.x * blockDim.x + threadIdx.x;
    if (i >= NNZ / 4) return;
    int4   r = grow4[i];
    int4   c = gcol4[i];
    float4 v = gval4[i];
    int p0 = atomicAdd(&d_cur[r.x], 1);
    int p1 = atomicAdd(&d_cur[r.y], 1);
    int p2 = atomicAdd(&d_cur[r.z], 1);
    int p3 = atomicAdd(&d_cur[r.w], 1);
    d_scv[p0] = make_float2(__int_as_float(c.x), v.x);
    d_scv[p1] = make_float2(__int_as_float(c.y), v.y);
    d_scv[p2] = make_float2(__int_as_float(c.z), v.z);
    d_scv[p3] = make_float2(__int_as_float(c.w), v.w);
}

// ---------------------------------------------------------------------------
// Gather SpMM, ONE WARP PER ROW. Each lane owns one uint32 = 2 bf16 elements
// (elements 2*lane, 2*lane+1). scv loads are warp-uniform broadcasts; feature
// loads are 128B coalesced per edge. No inter-row divergence inside a warp.
// ---------------------------------------------------------------------------
template <typename OUT>
__global__ void spmm_warp_row(const unsigned* __restrict__ feat,   // 32 uints/row
                              OUT*            __restrict__ xout) {
    int gwarp = (blockIdx.x * blockDim.x + threadIdx.x) >> 5;
    if (gwarp >= NTOT) return;
    int lane = threadIdx.x & 31;
    int s = d_rs[gwarp], e = d_rs[gwarp + 1];

    float ax = 0.f, ay = 0.f;
    int i = s;
    for (; i + 4 <= e; i += 4) {
        float2 p0 = d_scv[i],     p1 = d_scv[i + 1];
        float2 p2 = d_scv[i + 2], p3 = d_scv[i + 3];
        unsigned u0 = feat[(size_t)__float_as_int(p0.x) * 32 + lane];
        unsigned u1 = feat[(size_t)__float_as_int(p1.x) * 32 + lane];
        unsigned u2 = feat[(size_t)__float_as_int(p2.x) * 32 + lane];
        unsigned u3 = feat[(size_t)__float_as_int(p3.x) * 32 + lane];
        ax += p0.y * __uint_as_float(u0 << 16);
        ay += p0.y * __uint_as_float(u0 & 0xffff0000u);
        ax += p1.y * __uint_as_float(u1 << 16);
        ay += p1.y * __uint_as_float(u1 & 0xffff0000u);
        ax += p2.y * __uint_as_float(u2 << 16);
        ay += p2.y * __uint_as_float(u2 & 0xffff0000u);
        ax += p3.y * __uint_as_float(u3 << 16);
        ay += p3.y * __uint_as_float(u3 & 0xffff0000u);
    }
    for (; i < e; i++) {
        float2 p = d_scv[i];
        unsigned u = feat[(size_t)__float_as_int(p.x) * 32 + lane];
        ax += p.y * __uint_as_float(u << 16);
        ay += p.y * __uint_as_float(u & 0xffff0000u);
    }

    if (sizeof(OUT) == 2) {      // bf16 out: one packed uint per lane (128B/warp)
        __nv_bfloat162 o = __floats2bfloat162_rn(ax, ay);
        ((unsigned*)xout)[(size_t)gwarp * 32 + lane] = *(unsigned*)&o;
    } else {                     // fp32 out: float2 per lane (256B/warp)
        ((float2*)xout)[(size_t)gwarp * 32 + lane] = make_float2(ax, ay);
    }
}

// ---------------------------------------------------------------------------
// Tail: light = (emb + h1 + h2 + b3) / 4 at gathered rows, two 64x64 matvecs,
// softmax/sigmoid, dot. One warp per batch element.
// ---------------------------------------------------------------------------
__device__ __forceinline__ float bf2f(__nv_bfloat16 h) {
    return __uint_as_float(((unsigned)*(unsigned short*)&h) << 16);
}

__global__ void final_kernel(const float* __restrict__ eu,
                             const float* __restrict__ ei,
                             const float* __restrict__ w_user,
                             const float* __restrict__ w_item,
                             const float* __restrict__ xe1,
                             const float* __restrict__ xe0,
                             const int*   __restrict__ users,
                             const int*   __restrict__ items,
                             const int*   __restrict__ xij,
                             float*       __restrict__ out) {
    __shared__ float wu[64 * 65];
    __shared__ float wi[64 * 65];
    int tid = threadIdx.x;                     // 128 threads
    for (int idx = tid; idx < 64 * 64; idx += blockDim.x) {
        int r = idx >> 6, c = idx & 63;
        wu[r * 65 + c] = w_user[idx];
        wi[r * 65 + c] = w_item[idx];
    }
    __syncthreads();

    int warp = tid >> 5;
    int lane = tid & 31;

    int b_base = blockIdx.x * 32 + warp * 8;   // 512 blocks * 4 warps * 8
    for (int bi = 0; bi < 8; bi++) {
        int b = b_base + bi;
        int u  = users[b];
        int it = items[b];
        size_t uo = (size_t)u * 64;
        size_t io = (size_t)(N_USERS + it) * 64;
        size_t ie_off = (size_t)it * 64;

        float ue0 = (eu[uo + lane] + bf2f(d_h1[uo + lane]) +
                     bf2f(d_h2[uo + lane]) + d_b3[uo + lane]) * 0.25f;
        float ue1 = (eu[uo + 32 + lane] + bf2f(d_h1[uo + 32 + lane]) +
                     bf2f(d_h2[uo + 32 + lane]) + d_b3[uo + 32 + lane]) * 0.25f;
        float ie0 = (ei[ie_off + lane] + bf2f(d_h1[io + lane]) +
                     bf2f(d_h2[io + lane]) + d_b3[io + lane]) * 0.25f;
        float ie1 = (ei[ie_off + 32 + lane] + bf2f(d_h1[io + 32 + lane]) +
                     bf2f(d_h2[io + 32 + lane]) + d_b3[io + 32 + lane]) * 0.25f;

        float po0 = 0.f, po1 = 0.f, qo0 = 0.f, qo1 = 0.f;
        #pragma unroll
        for (int k = 0; k < 32; k++) {
            float au = __shfl_sync(0xffffffffu, ue0, k);
            float ai = __shfl_sync(0xffffffffu, ie0, k);
            po0 += au * wu[lane * 65 + k];
            po1 += au * wu[(lane + 32) * 65 + k];
            qo0 += ai * wi[lane * 65 + k];
            qo1 += ai * wi[(lane + 32) * 65 + k];
        }
        #pragma unroll
        for (int k = 0; k < 32; k++) {
            float au = __shfl_sync(0xffffffffu, ue1, k);
            float ai = __shfl_sync(0xffffffffu, ie1, k);
            po0 += au * wu[lane * 65 + 32 + k];
            po1 += au * wu[(lane + 32) * 65 + 32 + k];
            qo0 += ai * wi[lane * 65 + 32 + k];
            qo1 += ai * wi[(lane + 32) * 65 + 32 + k];
        }

        float m = fmaxf(po0, po1);
        #pragma unroll
        for (int o = 16; o; o >>= 1)
            m = fmaxf(m, __shfl_xor_sync(0xffffffffu, m, o));
        float e0 = expf(po0 - m);
        float e1 = expf(po1 - m);
        float s = e0 + e1;
        #pragma unroll
        for (int o = 16; o; o >>= 1)
            s += __shfl_xor_sync(0xffffffffu, s, o);
        float scale = 0.5f / s;                 // (1 - hx) * softmax

        float sg0 = 1.f / (1.f + expf(-qo0));
        float sg1 = 1.f / (1.f + expf(-qo1));

        float part = scale * (e0 * sg0 + e1 * sg1);
        #pragma unroll
        for (int o = 16; o; o >>= 1)
            part += __shfl_xor_sync(0xffffffffu, part, o);

        if (lane == 0) {
            float xe  = (xij[b] > 0) ? xe1[it] : xe0[it];
            float sgx = 1.f / (1.f + expf(-xe));
            out[b] = part + 0.5f * sgx;
        }
    }
}

// ---------------------------------------------------------------------------
extern "C" void kernel_launch(void* const* d_in, const int* in_sizes, int n_in,
                              void* d_out, int out_size) {
    (void)in_sizes; (void)n_in; (void)out_size;
    const float* emb_user = (const float*)d_in[0];
    const float* emb_item = (const float*)d_in[1];
    const float* w_user   = (const float*)d_in[2];
    const float* w_item   = (const float*)d_in[3];
    const float* xe1      = (const float*)d_in[4];
    const float* xe0      = (const float*)d_in[5];
    const float* g_val    = (const float*)d_in[6];
    const int*   g_row    = (const int*)d_in[7];
    const int*   g_col    = (const int*)d_in[8];
    const int*   users    = (const int*)d_in[9];
    const int*   items    = (const int*)d_in[10];
    const int*   xij      = (const int*)d_in[11];
    float* out = (float*)d_out;

    __nv_bfloat16 *p_h0, *p_h1, *p_h2;
    float *p_b3;
    cudaGetSymbolAddress((void**)&p_h0, d_h0);
    cudaGetSymbolAddress((void**)&p_h1, d_h1);
    cudaGetSymbolAddress((void**)&p_h2, d_h2);
    cudaGetSymbolAddress((void**)&p_b3, d_b3);

    const int nnz4Blocks = (NNZ / 4 + 255) / 256;
    const int spmmBlocks = (NTOT * 32 + 255) / 256;   // one warp per row
    const int k1Blocks   = CONV_BLOCKS + HIST_BLOCKS + 3;

    k1_fused<<<k1Blocks, 256>>>((const float4*)emb_user,
                                (const float4*)emb_item,
                                (const int4*)g_row);
    k2_scan_lookback<<<NTILES, 256>>>();
    k3_permute<<<nnz4Blocks, 256>>>((const int4*)g_row, (const int4*)g_col,
                                    (const float4*)g_val);
    spmm_warp_row<__nv_bfloat16><<<spmmBlocks, 256>>>((const unsigned*)p_h0, p_h1);
    spmm_warp_row<__nv_bfloat16><<<spmmBlocks, 256>>>((const unsigned*)p_h1, p_h2);
    spmm_warp_row<float        ><<<spmmBlocks, 256>>>((const unsigned*)p_h2, p_b3);
    final_kernel<<<BATCH / 32, 128>>>(emb_user, emb_item, w_user, w_item,
                                      xe1, xe0, users, items, xij, out);
}

// round 9
// speedup vs baseline: 1.2079x; 1.2079x over previous
#include <cuda_runtime.h>
#include <cuda_bf16.h>

#define N_USERS 100000
#define N_ITEMS 50000
#define NTOT    150000
#define D       64
#define NNZ     2000000
#define BATCH   16384
#define NTILES  586            // ceil(NTOT/256)
#define CONV_BLOCKS 4688       // NTOT*D/8/256
#define HIST_BLOCKS 1954       // ceil(NNZ/4/256)

// Scratch (allocation-free: __device__ globals; zero-initialized at load)
__device__ __nv_bfloat16 d_h0[NTOT * D];   // bf16 concat(emb_user, emb_item)
__device__ __nv_bfloat16 d_h1[NTOT * D];   // layer 1 output (bf16)
__device__ __nv_bfloat16 d_h2[NTOT * D];   // layer 2 output (bf16)
__device__ float   d_b3[NTOT * D];         // layer 3 output (fp32, never gathered)
__device__ int     d_cnt [NTOT];
__device__ int     d_cur [NTOT];
__device__ int     d_rs  [NTOT + 1];
__device__ unsigned long long d_tstate[NTILES];  // lookback states: flag<<32|val
__device__ float4  d_scv4[NNZ / 2];        // packed pairs of (col_bits, val)

// ---------------------------------------------------------------------------
// k1 (fused): tobf16 | histogram | lookback-state reset
// ---------------------------------------------------------------------------
__global__ void k1_fused(const float4* __restrict__ eu,
                         const float4* __restrict__ ei,
                         const int4*   __restrict__ grow4) {
    int bid = blockIdx.x;
    if (bid < CONV_BLOCKS) {
        int i = bid * 256 + threadIdx.x;            // chunk of 8 elements
        const int total8 = NTOT * D / 8;
        if (i >= total8) return;
        const int uhalf = N_USERS * D / 8;
        float4 a, b;
        if (i < uhalf) { a = eu[i * 2]; b = eu[i * 2 + 1]; }
        else { int j = i - uhalf; a = ei[j * 2]; b = ei[j * 2 + 1]; }
        __nv_bfloat162 h[4];
        h[0] = __floats2bfloat162_rn(a.x, a.y);
        h[1] = __floats2bfloat162_rn(a.z, a.w);
        h[2] = __floats2bfloat162_rn(b.x, b.y);
        h[3] = __floats2bfloat162_rn(b.z, b.w);
        ((uint4*)d_h0)[i] = *(uint4*)h;
    } else if (bid < CONV_BLOCKS + HIST_BLOCKS) {
        int i = (bid - CONV_BLOCKS) * 256 + threadIdx.x;
        if (i >= NNZ / 4) return;
        int4 r = grow4[i];
        atomicAdd(&d_cnt[r.x], 1);
        atomicAdd(&d_cnt[r.y], 1);
        atomicAdd(&d_cnt[r.z], 1);
        atomicAdd(&d_cnt[r.w], 1);
    } else {
        int i = (bid - CONV_BLOCKS - HIST_BLOCKS) * 256 + threadIdx.x;
        if (i < NTILES) d_tstate[i] = 0ULL;
    }
}

// ---------------------------------------------------------------------------
// k2: single-pass decoupled-lookback scan of d_cnt -> d_rs (exclusive).
// Also zeroes d_cnt for the next replay and initializes d_cur = d_rs.
// ---------------------------------------------------------------------------
__global__ void k2_scan_lookback() {
    __shared__ int ws[8];
    __shared__ int s_off;
    const int tile = blockIdx.x;
    const int i = tile * 256 + threadIdx.x;
    const int lane = threadIdx.x & 31, w = threadIdx.x >> 5;

    int c = (i < NTOT) ? d_cnt[i] : 0;
    if (i < NTOT) d_cnt[i] = 0;

    int x = c;
    #pragma unroll
    for (int o = 1; o < 32; o <<= 1) {
        int y = __shfl_up_sync(0xffffffffu, x, o);
        if (lane >= o) x += y;
    }
    if (lane == 31) ws[w] = x;
    __syncthreads();
    if (w == 0) {
        int s = (lane < 8) ? ws[lane] : 0;
        #pragma unroll
        for (int o = 1; o < 8; o <<= 1) {
            int y = __shfl_up_sync(0xffffffffu, s, o);
            if (lane >= o) s += y;
        }
        if (lane < 8) ws[lane] = s;
    }
    __syncthreads();
    int woff = (w > 0) ? ws[w - 1] : 0;
    int incl = x + woff;
    int total = ws[7];

    if (threadIdx.x == 0) {
        unsigned long long st = (tile == 0)
            ? ((2ULL << 32) | (unsigned)total)
            : ((1ULL << 32) | (unsigned)total);
        *(volatile unsigned long long*)&d_tstate[tile] = st;
    }

    if (w == 0) {
        int running = 0;
        int base = tile - 1;
        while (base >= 0) {
            int idx = base - lane;
            unsigned long long st;
            int flag;
            do {
                st = (idx >= 0)
                   ? *(volatile unsigned long long*)&d_tstate[idx]
                   : (2ULL << 32);
                flag = (int)(st >> 32);
            } while (__any_sync(0xffffffffu, flag == 0));
            int val = (int)(unsigned)st;
            unsigned mask = __ballot_sync(0xffffffffu, flag == 2);
            if (mask) {
                int k = __ffs(mask) - 1;
                int contrib = (lane <= k) ? val : 0;
                #pragma unroll
                for (int o = 16; o; o >>= 1)
                    contrib += __shfl_xor_sync(0xffffffffu, contrib, o);
                running += contrib;
                break;
            } else {
                int contrib = val;
                #pragma unroll
                for (int o = 16; o; o >>= 1)
                    contrib += __shfl_xor_sync(0xffffffffu, contrib, o);
                running += contrib;
                base -= 32;
            }
        }
        if (lane == 0) {
            s_off = running;
            if (tile > 0)
                *(volatile unsigned long long*)&d_tstate[tile] =
                    (2ULL << 32) | (unsigned)(running + total);
        }
    }
    __syncthreads();

    int excl = s_off + incl - c;
    if (i <= NTOT) d_rs[i] = excl;
    if (i < NTOT)  d_cur[i] = excl;
}

// ---------------------------------------------------------------------------
// k3: permute edges into CSR order (4 edges per thread, vectorized loads)
// ---------------------------------------------------------------------------
__global__ void k3_permute(const int4*   __restrict__ grow4,
                           const int4*   __restrict__ gcol4,
                           const float4* __restrict__ gval4) {
    int i = blockIdx.x * blockDim.x + threadIdx.x;
    if (i >= NNZ / 4) return;
    int4   r = grow4[i];
    int4   c = gcol4[i];
    float4 v = gval4[i];
    float2* scv = (float2*)d_scv4;
    int p0 = atomicAdd(&d_cur[r.x], 1);
    int p1 = atomicAdd(&d_cur[r.y], 1);
    int p2 = atomicAdd(&d_cur[r.z], 1);
    int p3 = atomicAdd(&d_cur[r.w], 1);
    scv[p0] = make_float2(__int_as_float(c.x), v.x);
    scv[p1] = make_float2(__int_as_float(c.y), v.y);
    scv[p2] = make_float2(__int_as_float(c.z), v.z);
    scv[p3] = make_float2(__int_as_float(c.w), v.w);
}

// ---------------------------------------------------------------------------
// Gather SpMM over bf16 features, packed f32x2 accumulation (FFMA2).
// 8 lanes per row, one uint4 (8 bf16) per lane; x4 edge unroll; scv read as
// float4 pairs (2 edges / LDG.128) after a 1-edge alignment peel.
// ---------------------------------------------------------------------------
__device__ __forceinline__ void fma8_x2(unsigned long long* acc, uint4 x,
                                        unsigned long long vv) {
    unsigned u[4] = {x.x, x.y, x.z, x.w};
    #pragma unroll
    for (int j = 0; j < 4; j++) {
        unsigned long long xf;
        asm("mov.b64 %0, {%1, %2};" : "=l"(xf)
            : "r"(u[j] << 16), "r"(u[j] & 0xffff0000u));
        asm("fma.rn.f32x2 %0, %1, %2, %3;"
            : "=l"(acc[j]) : "l"(xf), "l"(vv), "l"(acc[j]));
    }
}

__device__ __forceinline__ unsigned long long packvv(float v) {
    unsigned long long vv;
    asm("mov.b64 %0, {%1, %1};" : "=l"(vv) : "r"(__float_as_uint(v)));
    return vv;
}

template <typename OUT>
__global__ void __launch_bounds__(256, 8)
spmm_gather_h(const __nv_bfloat16* __restrict__ xin,
              OUT*                 __restrict__ xout) {
    int gid = blockIdx.x * blockDim.x + threadIdx.x;
    int row = gid >> 3;
    int t   = gid & 7;
    if (row >= NTOT) return;
    int s = d_rs[row], e = d_rs[row + 1];
    const uint4*  feat = (const uint4*)xin;      // 8 uint4 per row
    const float2* scv  = (const float2*)d_scv4;

    unsigned long long acc[4] = {0ULL, 0ULL, 0ULL, 0ULL};

    int i = s;
    // peel one edge to align i to an even index (float4 = 2 edges)
    if ((i & 1) && i < e) {
        float2 p = scv[i];
        uint4 x = feat[(size_t)__float_as_int(p.x) * 8 + t];
        fma8_x2(acc, x, packvv(p.y));
        i++;
    }
    for (; i + 4 <= e; i += 4) {
        float4 q0 = d_scv4[i >> 1];          // edges i, i+1
        float4 q1 = d_scv4[(i >> 1) + 1];    // edges i+2, i+3
        uint4 x0 = feat[(size_t)__float_as_int(q0.x) * 8 + t];
        uint4 x1 = feat[(size_t)__float_as_int(q0.z) * 8 + t];
        uint4 x2 = feat[(size_t)__float_as_int(q1.x) * 8 + t];
        uint4 x3 = feat[(size_t)__float_as_int(q1.z) * 8 + t];
        fma8_x2(acc, x0, packvv(q0.y));
        fma8_x2(acc, x1, packvv(q0.w));
        fma8_x2(acc, x2, packvv(q1.y));
        fma8_x2(acc, x3, packvv(q1.w));
    }
    for (; i < e; i++) {
        float2 p = scv[i];
        uint4 x = feat[(size_t)__float_as_int(p.x) * 8 + t];
        fma8_x2(acc, x, packvv(p.y));
    }

    // unpack accumulators (lo = element 2j, hi = element 2j+1)
    float a[8];
    #pragma unroll
    for (int j = 0; j < 4; j++) {
        a[2 * j]     = __uint_as_float((unsigned)(acc[j] & 0xffffffffu));
        a[2 * j + 1] = __uint_as_float((unsigned)(acc[j] >> 32));
    }

    size_t base = (size_t)row * 64 + t * 8;
    if (sizeof(OUT) == 2) {                     // bf16 output (packed cvt)
        __nv_bfloat162 o[4];
        #pragma unroll
        for (int j = 0; j < 4; j++)
            o[j] = __floats2bfloat162_rn(a[2 * j], a[2 * j + 1]);
        *(uint4*)((__nv_bfloat16*)xout + base) = *(uint4*)o;
    } else {                                    // fp32 output
        float4 o0 = make_float4(a[0], a[1], a[2], a[3]);
        float4 o1 = make_float4(a[4], a[5], a[6], a[7]);
        *(float4*)((float*)xout + base)     = o0;
        *(float4*)((float*)xout + base + 4) = o1;
    }
}

// ---------------------------------------------------------------------------
// Tail: light = (emb + h1 + h2 + b3) / 4 at gathered rows, two 64x64 matvecs,
// softmax/sigmoid, dot. One warp per batch element.
// ---------------------------------------------------------------------------
__device__ __forceinline__ float bf2f(__nv_bfloat16 h) {
    return __uint_as_float(((unsigned)*(unsigned short*)&h) << 16);
}

__global__ void final_kernel(const float* __restrict__ eu,
                             const float* __restrict__ ei,
                             const float* __restrict__ w_user,
                             const float* __restrict__ w_item,
                             const float* __restrict__ xe1,
                             const float* __restrict__ xe0,
                             const int*   __restrict__ users,
                             const int*   __restrict__ items,
                             const int*   __restrict__ xij,
                             float*       __restrict__ out) {
    __shared__ float wu[64 * 65];
    __shared__ float wi[64 * 65];
    int tid = threadIdx.x;                     // 128 threads
    for (int idx = tid; idx < 64 * 64; idx += blockDim.x) {
        int r = idx >> 6, c = idx & 63;
        wu[r * 65 + c] = w_user[idx];
        wi[r * 65 + c] = w_item[idx];
    }
    __syncthreads();

    int warp = tid >> 5;
    int lane = tid & 31;

    int b_base = blockIdx.x * 32 + warp * 8;   // 512 blocks * 4 warps * 8
    for (int bi = 0; bi < 8; bi++) {
        int b = b_base + bi;
        int u  = users[b];
        int it = items[b];
        size_t uo = (size_t)u * 64;
        size_t io = (size_t)(N_USERS + it) * 64;
        size_t ie_off = (size_t)it * 64;

        float ue0 = (eu[uo + lane] + bf2f(d_h1[uo + lane]) +
                     bf2f(d_h2[uo + lane]) + d_b3[uo + lane]) * 0.25f;
        float ue1 = (eu[uo + 32 + lane] + bf2f(d_h1[uo + 32 + lane]) +
                     bf2f(d_h2[uo + 32 + lane]) + d_b3[uo + 32 + lane]) * 0.25f;
        float ie0 = (ei[ie_off + lane] + bf2f(d_h1[io + lane]) +
                     bf2f(d_h2[io + lane]) + d_b3[io + lane]) * 0.25f;
        float ie1 = (ei[ie_off + 32 + lane] + bf2f(d_h1[io + 32 + lane]) +
                     bf2f(d_h2[io + 32 + lane]) + d_b3[io + 32 + lane]) * 0.25f;

        float po0 = 0.f, po1 = 0.f, qo0 = 0.f, qo1 = 0.f;
        #pragma unroll
        for (int k = 0; k < 32; k++) {
            float au = __shfl_sync(0xffffffffu, ue0, k);
            float ai = __shfl_sync(0xffffffffu, ie0, k);
            po0 += au * wu[lane * 65 + k];
            po1 += au * wu[(lane + 32) * 65 + k];
            qo0 += ai * wi[lane * 65 + k];
            qo1 += ai * wi[(lane + 32) * 65 + k];
        }
        #pragma unroll
        for (int k = 0; k < 32; k++) {
            float au = __shfl_sync(0xffffffffu, ue1, k);
            float ai = __shfl_sync(0xffffffffu, ie1, k);
            po0 += au * wu[lane * 65 + 32 + k];
            po1 += au * wu[(lane + 32) * 65 + 32 + k];
            qo0 += ai * wi[lane * 65 + 32 + k];
            qo1 += ai * wi[(lane + 32) * 65 + 32 + k];
        }

        float m = fmaxf(po0, po1);
        #pragma unroll
        for (int o = 16; o; o >>= 1)
            m = fmaxf(m, __shfl_xor_sync(0xffffffffu, m, o));
        float e0 = expf(po0 - m);
        float e1 = expf(po1 - m);
        float s = e0 + e1;
        #pragma unroll
        for (int o = 16; o; o >>= 1)
            s += __shfl_xor_sync(0xffffffffu, s, o);
        float scale = 0.5f / s;                 // (1 - hx) * softmax

        float sg0 = 1.f / (1.f + expf(-qo0));
        float sg1 = 1.f / (1.f + expf(-qo1));

        float part = scale * (e0 * sg0 + e1 * sg1);
        #pragma unroll
        for (int o = 16; o; o >>= 1)
            part += __shfl_xor_sync(0xffffffffu, part, o);

        if (lane == 0) {
            float xe  = (xij[b] > 0) ? xe1[it] : xe0[it];
            float sgx = 1.f / (1.f + expf(-xe));
            out[b] = part + 0.5f * sgx;
        }
    }
}

// ---------------------------------------------------------------------------
extern "C" void kernel_launch(void* const* d_in, const int* in_sizes, int n_in,
                              void* d_out, int out_size) {
    (void)in_sizes; (void)n_in; (void)out_size;
    const float* emb_user = (const float*)d_in[0];
    const float* emb_item = (const float*)d_in[1];
    const float* w_user   = (const float*)d_in[2];
    const float* w_item   = (const float*)d_in[3];
    const float* xe1      = (const float*)d_in[4];
    const float* xe0      = (const float*)d_in[5];
    const float* g_val    = (const float*)d_in[6];
    const int*   g_row    = (const int*)d_in[7];
    const int*   g_col    = (const int*)d_in[8];
    const int*   users    = (const int*)d_in[9];
    const int*   items    = (const int*)d_in[10];
    const int*   xij      = (const int*)d_in[11];
    float* out = (float*)d_out;

    __nv_bfloat16 *p_h0, *p_h1, *p_h2;
    float *p_b3;
    cudaGetSymbolAddress((void**)&p_h0, d_h0);
    cudaGetSymbolAddress((void**)&p_h1, d_h1);
    cudaGetSymbolAddress((void**)&p_h2, d_h2);
    cudaGetSymbolAddress((void**)&p_b3, d_b3);

    const int nnz4Blocks   = (NNZ / 4 + 255) / 256;
    const int gatherBlocks = (NTOT * 8 + 255) / 256;
    const int k1Blocks     = CONV_BLOCKS + HIST_BLOCKS + 3;

    k1_fused<<<k1Blocks, 256>>>((const float4*)emb_user,
                                (const float4*)emb_item,
                                (const int4*)g_row);
    k2_scan_lookback<<<NTILES, 256>>>();
    k3_permute<<<nnz4Blocks, 256>>>((const int4*)g_row, (const int4*)g_col,
                                    (const float4*)g_val);
    spmm_gather_h<__nv_bfloat16><<<gatherBlocks, 256>>>(p_h0, p_h1);
    spmm_gather_h<__nv_bfloat16><<<gatherBlocks, 256>>>(p_h1, p_h2);
    spmm_gather_h<float        ><<<gatherBlocks, 256>>>(p_h2, p_b3);
    final_kernel<<<BATCH / 32, 128>>>(emb_user, emb_item, w_user, w_item,
                                      xe1, xe0, users, items, xij, out);
}